// round 3
// baseline (speedup 1.0000x reference)
#include <cuda_runtime.h>

#define NUM_USERS 100000
#define NUM_ITEMS 50000
#define N_NODES   150000
#define C         64
#define NNZ       2400000
#define BATCH     8192
#define NEG_SLOPE 0.1f
#define EPS       1e-12f

// Propagation state
__device__ float g_bufA[(size_t)N_NODES * C];
__device__ float g_bufB[(size_t)N_NODES * C];
__device__ float g_acc [(size_t)N_NODES * C];

// CSR scratch (rebuilt every call)
__device__ int  g_rowptr[N_NODES + 1];
__device__ int  g_off   [N_NODES];
__device__ int2 g_csr   [NNZ];       // {col, float_as_int(val)} interleaved

__device__ __forceinline__ float lrelu(float x) {
    return x >= 0.0f ? x : NEG_SLOPE * x;
}

__device__ __forceinline__ float warp_sum(float s) {
#pragma unroll
    for (int o = 16; o; o >>= 1) s += __shfl_xor_sync(0xffffffffu, s, o);
    return s;
}

// ---------------- CSR build ----------------

__global__ __launch_bounds__(256) void k_zero_counts() {
    int i = blockIdx.x * blockDim.x + threadIdx.x;
    if (i <= N_NODES) g_rowptr[i] = 0;
}

__global__ __launch_bounds__(256) void k_hist(const int* __restrict__ erow) {
    int e = blockIdx.x * blockDim.x + threadIdx.x;
    if (e < NNZ) atomicAdd(&g_rowptr[erow[e] + 1], 1);
}

// Single-block scan over N_NODES+1 entries.
__global__ __launch_bounds__(1024) void k_scan() {
    __shared__ int sums[1024];
    const int NTOT = N_NODES + 1;
    int t = threadIdx.x;
    int per = (NTOT + 1023) / 1024;
    int beg = t * per;
    int end = min(beg + per, NTOT);

    int run = 0;
    for (int i = beg; i < end; ++i) { run += g_rowptr[i]; g_rowptr[i] = run; }
    sums[t] = run;
    __syncthreads();
#pragma unroll
    for (int off = 1; off < 1024; off <<= 1) {
        int v = (t >= off) ? sums[t - off] : 0;
        __syncthreads();
        sums[t] += v;
        __syncthreads();
    }
    int offset = (t > 0) ? sums[t - 1] : 0;
    for (int i = beg; i < end; ++i) {
        int v = g_rowptr[i] + offset;
        g_rowptr[i] = v;
        if (i < N_NODES) g_off[i] = v;
    }
}

__global__ __launch_bounds__(256) void k_scatter(const int* __restrict__ erow,
                                                 const int* __restrict__ ecol,
                                                 const float* __restrict__ eval) {
    int e = blockIdx.x * blockDim.x + threadIdx.x;
    if (e >= NNZ) return;
    int r = erow[e];
    int pos = atomicAdd(&g_off[r], 1);
    g_csr[pos] = make_int2(ecol[e], __float_as_int(eval[e]));
}

// ---------------- init ----------------

__global__ __launch_bounds__(256) void k_init(const float* __restrict__ up,
                                              const float* __restrict__ ip) {
    int row = blockIdx.x * (blockDim.x >> 5) + (threadIdx.x >> 5);
    if (row >= N_NODES) return;
    int lane = threadIdx.x & 31;

    const float* src = (row < NUM_USERS)
                           ? (up + (size_t)row * C)
                           : (ip + (size_t)(row - NUM_USERS) * C);
    float2 v = reinterpret_cast<const float2*>(src)[lane];
    v.x = lrelu(v.x);
    v.y = lrelu(v.y);
    float s = warp_sum(v.x * v.x + v.y * v.y);
    float inv = 1.0f / fmaxf(sqrtf(s), EPS);
    v.x *= inv; v.y *= inv;

    size_t idx = (size_t)row * 32 + lane;
    reinterpret_cast<float2*>(g_bufA)[idx] = v;
    reinterpret_cast<float2*>(g_acc)[idx]  = v;
}

// ---------------- fused layer: gather-SpMM + lrelu + l2norm + acc ----------------
// One warp per row. Lanes hold 2 features each (float2).
// Edge metadata loaded as uniform broadcast (all lanes same address, L1-hit);
// 4-way unroll with 4 independent accumulator pairs for MLP + FMA-chain break.

__global__ __launch_bounds__(256) void k_layer(int flip) {
    const float* __restrict__ p  = flip ? g_bufB : g_bufA;
    float* __restrict__       pn = flip ? g_bufA : g_bufB;

    int row = blockIdx.x * (blockDim.x >> 5) + (threadIdx.x >> 5);
    if (row >= N_NODES) return;
    int lane = threadIdx.x & 31;

    int i   = g_rowptr[row];
    int end = g_rowptr[row + 1];

    const float2* __restrict__ p2  = reinterpret_cast<const float2*>(p);
    const int2*   __restrict__ csr = g_csr;

    float2 s0 = make_float2(0.f, 0.f);
    float2 s1 = make_float2(0.f, 0.f);
    float2 s2 = make_float2(0.f, 0.f);
    float2 s3 = make_float2(0.f, 0.f);

    for (; i + 4 <= end; i += 4) {
        int2 e0 = __ldg(csr + i + 0);
        int2 e1 = __ldg(csr + i + 1);
        int2 e2 = __ldg(csr + i + 2);
        int2 e3 = __ldg(csr + i + 3);
        float2 x0 = __ldg(p2 + (size_t)e0.x * 32 + lane);
        float2 x1 = __ldg(p2 + (size_t)e1.x * 32 + lane);
        float2 x2 = __ldg(p2 + (size_t)e2.x * 32 + lane);
        float2 x3 = __ldg(p2 + (size_t)e3.x * 32 + lane);
        float v0 = __int_as_float(e0.y);
        float v1 = __int_as_float(e1.y);
        float v2 = __int_as_float(e2.y);
        float v3 = __int_as_float(e3.y);
        s0.x = fmaf(v0, x0.x, s0.x); s0.y = fmaf(v0, x0.y, s0.y);
        s1.x = fmaf(v1, x1.x, s1.x); s1.y = fmaf(v1, x1.y, s1.y);
        s2.x = fmaf(v2, x2.x, s2.x); s2.y = fmaf(v2, x2.y, s2.y);
        s3.x = fmaf(v3, x3.x, s3.x); s3.y = fmaf(v3, x3.y, s3.y);
    }
    for (; i < end; ++i) {
        int2 e = __ldg(csr + i);
        float2 x = __ldg(p2 + (size_t)e.x * 32 + lane);
        float v = __int_as_float(e.y);
        s0.x = fmaf(v, x.x, s0.x); s0.y = fmaf(v, x.y, s0.y);
    }

    float2 s;
    s.x = (s0.x + s1.x) + (s2.x + s3.x);
    s.y = (s0.y + s1.y) + (s2.y + s3.y);

    s.x = lrelu(s.x);
    s.y = lrelu(s.y);
    float nrm = warp_sum(s.x * s.x + s.y * s.y);
    float inv = 1.0f / fmaxf(sqrtf(nrm), EPS);
    s.x *= inv; s.y *= inv;

    size_t idx = (size_t)row * 32 + lane;
    reinterpret_cast<float2*>(pn)[idx] = s;
    float2 a = reinterpret_cast<float2*>(g_acc)[idx];
    a.x += s.x; a.y += s.y;
    reinterpret_cast<float2*>(g_acc)[idx] = a;
}

// ---------------- scoring ----------------

__global__ __launch_bounds__(256) void k_score(const int* __restrict__ users,
                                               const int* __restrict__ adj,
                                               const int* __restrict__ weak,
                                               const int* __restrict__ strong,
                                               float* __restrict__ out) {
    int b = blockIdx.x * (blockDim.x >> 5) + (threadIdx.x >> 5);
    if (b >= BATCH) return;
    int lane = threadIdx.x & 31;

    const float2* acc2 = reinterpret_cast<const float2*>(g_acc);
    int u  = users[b];
    int i0 = NUM_USERS + adj[b];
    int i1 = NUM_USERS + weak[b];
    int i2 = NUM_USERS + strong[b];

    float2 uv = acc2[(size_t)u  * 32 + lane];
    float2 a0 = acc2[(size_t)i0 * 32 + lane];
    float2 a1 = acc2[(size_t)i1 * 32 + lane];
    float2 a2 = acc2[(size_t)i2 * 32 + lane];

    float d0 = warp_sum(uv.x * a0.x + uv.y * a0.y);
    float d1 = warp_sum(uv.x * a1.x + uv.y * a1.y);
    float d2 = warp_sum(uv.x * a2.x + uv.y * a2.y);

    if (lane == 0) {
        out[0 * BATCH + b] = 1.0f / (1.0f + expf(-d0 * (1.0f / 16.0f)));
        out[1 * BATCH + b] = 1.0f / (1.0f + expf(-d1 * (1.0f / 16.0f)));
        out[2 * BATCH + b] = 1.0f / (1.0f + expf(-d2 * (1.0f / 16.0f)));
    }
}

extern "C" void kernel_launch(void* const* d_in, const int* in_sizes, int n_in,
                              void* d_out, int out_size) {
    const int*   users  = (const int*)d_in[0];
    const int*   adj    = (const int*)d_in[1];
    const int*   weak   = (const int*)d_in[2];
    const int*   strong = (const int*)d_in[3];
    const int*   erow   = (const int*)d_in[4];
    const int*   ecol   = (const int*)d_in[5];
    const float* eval   = (const float*)d_in[6];
    const float* up     = (const float*)d_in[7];
    const float* ip     = (const float*)d_in[8];
    float* out = (float*)d_out;

    const int ROWS_BLOCKS = (N_NODES + 7) / 8;          // 8 warps/block
    const int EDGE_BLOCKS = (NNZ + 255) / 256;

    // CSR build
    k_zero_counts<<<(N_NODES + 256) / 256, 256>>>();
    k_hist<<<EDGE_BLOCKS, 256>>>(erow);
    k_scan<<<1, 1024>>>();
    k_scatter<<<EDGE_BLOCKS, 256>>>(erow, ecol, eval);

    // init normalized preferences
    k_init<<<ROWS_BLOCKS, 256>>>(up, ip);

    // 3 fused propagation layers
    int flip = 0;
    for (int layer = 0; layer < 3; ++layer) {
        k_layer<<<ROWS_BLOCKS, 256>>>(flip);
        flip ^= 1;
    }

    k_score<<<(BATCH + 7) / 8, 256>>>(users, adj, weak, strong, out);
}

// round 4
// speedup vs baseline: 1.0088x; 1.0088x over previous
#include <cuda_runtime.h>

#define NUM_USERS 100000
#define NUM_ITEMS 50000
#define N_NODES   150000
#define C         64
#define NNZ       2400000
#define BATCH     8192
#define NEG_SLOPE 0.1f
#define EPS       1e-12f

// Propagation state
__device__ float g_bufA[(size_t)N_NODES * C];
__device__ float g_bufB[(size_t)N_NODES * C];
__device__ float g_acc [(size_t)N_NODES * C];

// CSR scratch (rebuilt every call)
__device__ int  g_rowptr[N_NODES + 1];
__device__ int  g_off   [N_NODES];
__device__ int2 g_csr   [NNZ];       // {col, float_as_int(val)}

__device__ __forceinline__ float lrelu(float x) {
    return x >= 0.0f ? x : NEG_SLOPE * x;
}

__device__ __forceinline__ float warp_sum(float s) {
#pragma unroll
    for (int o = 16; o; o >>= 1) s += __shfl_xor_sync(0xffffffffu, s, o);
    return s;
}

// ---------------- CSR build ----------------

__global__ __launch_bounds__(256) void k_zero_counts() {
    int i = blockIdx.x * blockDim.x + threadIdx.x;
    if (i <= N_NODES) g_rowptr[i] = 0;
}

// 4 edges per thread (NNZ divisible by 4)
__global__ __launch_bounds__(256) void k_hist(const int* __restrict__ erow) {
    int i = (blockIdx.x * blockDim.x + threadIdx.x) * 4;
    if (i >= NNZ) return;
    int4 r = __ldcs(reinterpret_cast<const int4*>(erow + i));
    atomicAdd(&g_rowptr[r.x + 1], 1);
    atomicAdd(&g_rowptr[r.y + 1], 1);
    atomicAdd(&g_rowptr[r.z + 1], 1);
    atomicAdd(&g_rowptr[r.w + 1], 1);
}

// Single-block scan over N_NODES+1 entries.
__global__ __launch_bounds__(1024) void k_scan() {
    __shared__ int sums[1024];
    const int NTOT = N_NODES + 1;
    int t = threadIdx.x;
    int per = (NTOT + 1023) / 1024;
    int beg = t * per;
    int end = min(beg + per, NTOT);

    int run = 0;
    for (int i = beg; i < end; ++i) { run += g_rowptr[i]; g_rowptr[i] = run; }
    sums[t] = run;
    __syncthreads();
#pragma unroll
    for (int off = 1; off < 1024; off <<= 1) {
        int v = (t >= off) ? sums[t - off] : 0;
        __syncthreads();
        sums[t] += v;
        __syncthreads();
    }
    int offset = (t > 0) ? sums[t - 1] : 0;
    for (int i = beg; i < end; ++i) {
        int v = g_rowptr[i] + offset;
        g_rowptr[i] = v;
        if (i < N_NODES) g_off[i] = v;
    }
}

// 4 edges per thread, streaming loads, non-temporal stores
__global__ __launch_bounds__(256) void k_scatter(const int* __restrict__ erow,
                                                 const int* __restrict__ ecol,
                                                 const float* __restrict__ eval) {
    int i = (blockIdx.x * blockDim.x + threadIdx.x) * 4;
    if (i >= NNZ) return;
    int4   r = __ldcs(reinterpret_cast<const int4*>(erow + i));
    int4   c = __ldcs(reinterpret_cast<const int4*>(ecol + i));
    float4 v = __ldcs(reinterpret_cast<const float4*>(eval + i));
    int p0 = atomicAdd(&g_off[r.x], 1);
    int p1 = atomicAdd(&g_off[r.y], 1);
    int p2 = atomicAdd(&g_off[r.z], 1);
    int p3 = atomicAdd(&g_off[r.w], 1);
    __stcs(&g_csr[p0], make_int2(c.x, __float_as_int(v.x)));
    __stcs(&g_csr[p1], make_int2(c.y, __float_as_int(v.y)));
    __stcs(&g_csr[p2], make_int2(c.z, __float_as_int(v.z)));
    __stcs(&g_csr[p3], make_int2(c.w, __float_as_int(v.w)));
}

// ---------------- init ----------------

__global__ __launch_bounds__(256) void k_init(const float* __restrict__ up,
                                              const float* __restrict__ ip) {
    int row = blockIdx.x * (blockDim.x >> 5) + (threadIdx.x >> 5);
    if (row >= N_NODES) return;
    int lane = threadIdx.x & 31;

    const float* src = (row < NUM_USERS)
                           ? (up + (size_t)row * C)
                           : (ip + (size_t)(row - NUM_USERS) * C);
    float2 v = reinterpret_cast<const float2*>(src)[lane];
    v.x = lrelu(v.x);
    v.y = lrelu(v.y);
    float s = warp_sum(v.x * v.x + v.y * v.y);
    float inv = 1.0f / fmaxf(sqrtf(s), EPS);
    v.x *= inv; v.y *= inv;

    size_t idx = (size_t)row * 32 + lane;
    reinterpret_cast<float2*>(g_bufA)[idx] = v;
    __stcs(&reinterpret_cast<float2*>(g_acc)[idx], v);
}

// ---------------- fused layer ----------------
// One warp per row, lanes hold 2 features (float2).
// CSR entries staged through smem: coalesced __ldcs batch load of 32 edges,
// broadcast LDS re-reads. 4 independent accumulators. acc streamed (ldcs/stcs).

__global__ __launch_bounds__(256) void k_layer(int flip) {
    const float* __restrict__ p  = flip ? g_bufB : g_bufA;
    float* __restrict__       pn = flip ? g_bufA : g_bufB;

    __shared__ int2 se[8][32];

    int warp = threadIdx.x >> 5;
    int row  = blockIdx.x * 8 + warp;
    if (row >= N_NODES) return;
    int lane = threadIdx.x & 31;

    int beg = g_rowptr[row];
    int end = g_rowptr[row + 1];

    const float2* __restrict__ p2 = reinterpret_cast<const float2*>(p);

    float2 s0 = make_float2(0.f, 0.f);
    float2 s1 = make_float2(0.f, 0.f);
    float2 s2 = make_float2(0.f, 0.f);
    float2 s3 = make_float2(0.f, 0.f);

    for (int base = beg; base < end; base += 32) {
        int n = min(32, end - base);
        if (lane < n) se[warp][lane] = __ldcs(&g_csr[base + lane]);
        __syncwarp();

        int j = 0;
        for (; j + 4 <= n; j += 4) {
            int2 e0 = se[warp][j + 0];
            int2 e1 = se[warp][j + 1];
            int2 e2 = se[warp][j + 2];
            int2 e3 = se[warp][j + 3];
            float2 x0 = p2[(size_t)e0.x * 32 + lane];
            float2 x1 = p2[(size_t)e1.x * 32 + lane];
            float2 x2 = p2[(size_t)e2.x * 32 + lane];
            float2 x3 = p2[(size_t)e3.x * 32 + lane];
            float v0 = __int_as_float(e0.y);
            float v1 = __int_as_float(e1.y);
            float v2 = __int_as_float(e2.y);
            float v3 = __int_as_float(e3.y);
            s0.x = fmaf(v0, x0.x, s0.x); s0.y = fmaf(v0, x0.y, s0.y);
            s1.x = fmaf(v1, x1.x, s1.x); s1.y = fmaf(v1, x1.y, s1.y);
            s2.x = fmaf(v2, x2.x, s2.x); s2.y = fmaf(v2, x2.y, s2.y);
            s3.x = fmaf(v3, x3.x, s3.x); s3.y = fmaf(v3, x3.y, s3.y);
        }
        for (; j < n; ++j) {
            int2 e = se[warp][j];
            float2 x = p2[(size_t)e.x * 32 + lane];
            float v = __int_as_float(e.y);
            s0.x = fmaf(v, x.x, s0.x); s0.y = fmaf(v, x.y, s0.y);
        }
        __syncwarp();
    }

    float2 s;
    s.x = (s0.x + s1.x) + (s2.x + s3.x);
    s.y = (s0.y + s1.y) + (s2.y + s3.y);

    s.x = lrelu(s.x);
    s.y = lrelu(s.y);
    float nrm = warp_sum(s.x * s.x + s.y * s.y);
    float inv = 1.0f / fmaxf(sqrtf(nrm), EPS);
    s.x *= inv; s.y *= inv;

    size_t idx = (size_t)row * 32 + lane;
    reinterpret_cast<float2*>(pn)[idx] = s;
    float2* accp = &reinterpret_cast<float2*>(g_acc)[idx];
    float2 a = __ldcs(accp);
    a.x += s.x; a.y += s.y;
    __stcs(accp, a);
}

// ---------------- scoring ----------------

__global__ __launch_bounds__(256) void k_score(const int* __restrict__ users,
                                               const int* __restrict__ adj,
                                               const int* __restrict__ weak,
                                               const int* __restrict__ strong,
                                               float* __restrict__ out) {
    int b = blockIdx.x * (blockDim.x >> 5) + (threadIdx.x >> 5);
    if (b >= BATCH) return;
    int lane = threadIdx.x & 31;

    const float2* acc2 = reinterpret_cast<const float2*>(g_acc);
    int u  = users[b];
    int i0 = NUM_USERS + adj[b];
    int i1 = NUM_USERS + weak[b];
    int i2 = NUM_USERS + strong[b];

    float2 uv = acc2[(size_t)u  * 32 + lane];
    float2 a0 = acc2[(size_t)i0 * 32 + lane];
    float2 a1 = acc2[(size_t)i1 * 32 + lane];
    float2 a2 = acc2[(size_t)i2 * 32 + lane];

    float d0 = warp_sum(uv.x * a0.x + uv.y * a0.y);
    float d1 = warp_sum(uv.x * a1.x + uv.y * a1.y);
    float d2 = warp_sum(uv.x * a2.x + uv.y * a2.y);

    if (lane == 0) {
        out[0 * BATCH + b] = 1.0f / (1.0f + expf(-d0 * (1.0f / 16.0f)));
        out[1 * BATCH + b] = 1.0f / (1.0f + expf(-d1 * (1.0f / 16.0f)));
        out[2 * BATCH + b] = 1.0f / (1.0f + expf(-d2 * (1.0f / 16.0f)));
    }
}

extern "C" void kernel_launch(void* const* d_in, const int* in_sizes, int n_in,
                              void* d_out, int out_size) {
    const int*   users  = (const int*)d_in[0];
    const int*   adj    = (const int*)d_in[1];
    const int*   weak   = (const int*)d_in[2];
    const int*   strong = (const int*)d_in[3];
    const int*   erow   = (const int*)d_in[4];
    const int*   ecol   = (const int*)d_in[5];
    const float* eval   = (const float*)d_in[6];
    const float* up     = (const float*)d_in[7];
    const float* ip     = (const float*)d_in[8];
    float* out = (float*)d_out;

    const int ROWS_BLOCKS = (N_NODES + 7) / 8;     // 8 warps/block
    const int EDGE4_BLOCKS = (NNZ / 4 + 255) / 256;

    // CSR build
    k_zero_counts<<<(N_NODES + 256) / 256, 256>>>();
    k_hist<<<EDGE4_BLOCKS, 256>>>(erow);
    k_scan<<<1, 1024>>>();
    k_scatter<<<EDGE4_BLOCKS, 256>>>(erow, ecol, eval);

    // init normalized preferences
    k_init<<<ROWS_BLOCKS, 256>>>(up, ip);

    // 3 fused propagation layers
    int flip = 0;
    for (int layer = 0; layer < 3; ++layer) {
        k_layer<<<ROWS_BLOCKS, 256>>>(flip);
        flip ^= 1;
    }

    k_score<<<(BATCH + 7) / 8, 256>>>(users, adj, weak, strong, out);
}

// round 5
// speedup vs baseline: 1.5852x; 1.5714x over previous
#include <cuda_runtime.h>

#define NUM_USERS 100000
#define NUM_ITEMS 50000
#define N_NODES   150000
#define C         64
#define NNZ       2400000
#define BATCH     8192
#define NEG_SLOPE 0.1f
#define EPS       1e-12f

// Per-layer propagation outputs: p[0]=normalized prefs, p[1..2]=normalized
// layer outputs, p[3]=RAW layer-3 scatter output (normalized on the fly in
// k_score). merged = (p0+p1+p2+norm(p3))/4, only needed at batch rows.
__device__ float g_p[4][(size_t)N_NODES * C];

__device__ __forceinline__ float lrelu(float x) {
    return x >= 0.0f ? x : NEG_SLOPE * x;
}

__device__ __forceinline__ float warp_sum(float s) {
#pragma unroll
    for (int o = 16; o; o >>= 1) s += __shfl_xor_sync(0xffffffffu, s, o);
    return s;
}

// ---------------- init: normalize prefs -> p0, zero p1 ----------------
__global__ __launch_bounds__(256) void k_init(const float* __restrict__ up,
                                              const float* __restrict__ ip) {
    int row = blockIdx.x * (blockDim.x >> 5) + (threadIdx.x >> 5);
    if (row >= N_NODES) return;
    int lane = threadIdx.x & 31;

    const float* src = (row < NUM_USERS)
                           ? (up + (size_t)row * C)
                           : (ip + (size_t)(row - NUM_USERS) * C);
    float2 v = reinterpret_cast<const float2*>(src)[lane];
    v.x = lrelu(v.x);
    v.y = lrelu(v.y);
    float s = warp_sum(v.x * v.x + v.y * v.y);
    float inv = 1.0f / fmaxf(sqrtf(s), EPS);
    v.x *= inv; v.y *= inv;

    size_t idx = (size_t)row * 32 + lane;
    reinterpret_cast<float2*>(g_p[0])[idx] = v;
    reinterpret_cast<float2*>(g_p[1])[idx] = make_float2(0.0f, 0.0f);
}

// ---------------- SpMM scatter: 16 threads/edge, 2 edges per thread ----------------
// Reads g_p[layer-1], RED-accumulates into g_p[layer] (pre-zeroed).
__global__ __launch_bounds__(256) void k_spmm(const int* __restrict__ erow,
                                              const int* __restrict__ ecol,
                                              const float* __restrict__ eval,
                                              int layer) {
    const float* __restrict__ p  = g_p[layer - 1];
    float* __restrict__       pn = g_p[layer];

    int tid = blockIdx.x * blockDim.x + threadIdx.x;
    int e0 = tid >> 4;
    int q  = tid & 15;
    if (e0 >= NNZ / 2) return;
    int e1 = e0 + NNZ / 2;

    int   r0 = erow[e0], c0 = ecol[e0];
    int   r1 = erow[e1], c1 = ecol[e1];
    float v0 = eval[e0], v1 = eval[e1];

    float4 x0 = __ldg(reinterpret_cast<const float4*>(p + (size_t)c0 * C) + q);
    float4 x1 = __ldg(reinterpret_cast<const float4*>(p + (size_t)c1 * C) + q);

    x0.x *= v0; x0.y *= v0; x0.z *= v0; x0.w *= v0;
    x1.x *= v1; x1.y *= v1; x1.z *= v1; x1.w *= v1;

    float* d0 = pn + (size_t)r0 * C + q * 4;
    float* d1 = pn + (size_t)r1 * C + q * 4;
    asm volatile("red.global.add.v4.f32 [%0], {%1,%2,%3,%4};"
                 :: "l"(d0), "f"(x0.x), "f"(x0.y), "f"(x0.z), "f"(x0.w) : "memory");
    asm volatile("red.global.add.v4.f32 [%0], {%1,%2,%3,%4};"
                 :: "l"(d1), "f"(x1.x), "f"(x1.y), "f"(x1.z), "f"(x1.w) : "memory");
}

// ---------------- norm: lrelu+l2norm g_p[layer] in place, zero g_p[layer+1] ----------------
__global__ __launch_bounds__(256) void k_norm(int layer) {
    float* __restrict__ pn = g_p[layer];
    float* __restrict__ pz = g_p[layer + 1];

    int row = blockIdx.x * (blockDim.x >> 5) + (threadIdx.x >> 5);
    if (row >= N_NODES) return;
    int lane = threadIdx.x & 31;
    size_t idx = (size_t)row * 32 + lane;

    float2 v = reinterpret_cast<float2*>(pn)[idx];
    v.x = lrelu(v.x);
    v.y = lrelu(v.y);
    float s = warp_sum(v.x * v.x + v.y * v.y);
    float inv = 1.0f / fmaxf(sqrtf(s), EPS);
    v.x *= inv; v.y *= inv;

    reinterpret_cast<float2*>(pn)[idx] = v;
    reinterpret_cast<float2*>(pz)[idx] = make_float2(0.0f, 0.0f);
}

// ---------------- scoring: gather p0..p3 at needed rows ----------------
// One warp per batch element. p3 is raw -> lrelu + l2norm on the fly.
__device__ __forceinline__ float2 merged_row(int row, int lane) {
    const float2* b0 = reinterpret_cast<const float2*>(g_p[0]);
    const float2* b1 = reinterpret_cast<const float2*>(g_p[1]);
    const float2* b2 = reinterpret_cast<const float2*>(g_p[2]);
    const float2* b3 = reinterpret_cast<const float2*>(g_p[3]);
    size_t idx = (size_t)row * 32 + lane;

    float2 a0 = __ldg(b0 + idx);
    float2 a1 = __ldg(b1 + idx);
    float2 a2 = __ldg(b2 + idx);
    float2 a3 = __ldg(b3 + idx);

    a3.x = lrelu(a3.x);
    a3.y = lrelu(a3.y);
    float s = warp_sum(a3.x * a3.x + a3.y * a3.y);
    float inv = 1.0f / fmaxf(sqrtf(s), EPS);

    float2 m;
    m.x = a0.x + a1.x + a2.x + a3.x * inv;
    m.y = a0.y + a1.y + a2.y + a3.y * inv;
    return m;
}

__global__ __launch_bounds__(256) void k_score(const int* __restrict__ users,
                                               const int* __restrict__ adj,
                                               const int* __restrict__ weak,
                                               const int* __restrict__ strong,
                                               float* __restrict__ out) {
    int b = blockIdx.x * (blockDim.x >> 5) + (threadIdx.x >> 5);
    if (b >= BATCH) return;
    int lane = threadIdx.x & 31;

    float2 uv = merged_row(users[b], lane);
    float2 m0 = merged_row(NUM_USERS + adj[b], lane);
    float2 m1 = merged_row(NUM_USERS + weak[b], lane);
    float2 m2 = merged_row(NUM_USERS + strong[b], lane);

    float d0 = warp_sum(uv.x * m0.x + uv.y * m0.y);
    float d1 = warp_sum(uv.x * m1.x + uv.y * m1.y);
    float d2 = warp_sum(uv.x * m2.x + uv.y * m2.y);

    if (lane == 0) {
        out[0 * BATCH + b] = 1.0f / (1.0f + expf(-d0 * (1.0f / 16.0f)));
        out[1 * BATCH + b] = 1.0f / (1.0f + expf(-d1 * (1.0f / 16.0f)));
        out[2 * BATCH + b] = 1.0f / (1.0f + expf(-d2 * (1.0f / 16.0f)));
    }
}

extern "C" void kernel_launch(void* const* d_in, const int* in_sizes, int n_in,
                              void* d_out, int out_size) {
    const int*   users  = (const int*)d_in[0];
    const int*   adj    = (const int*)d_in[1];
    const int*   weak   = (const int*)d_in[2];
    const int*   strong = (const int*)d_in[3];
    const int*   erow   = (const int*)d_in[4];
    const int*   ecol   = (const int*)d_in[5];
    const float* eval   = (const float*)d_in[6];
    const float* up     = (const float*)d_in[7];
    const float* ip     = (const float*)d_in[8];
    float* out = (float*)d_out;

    const int ROWS_BLOCKS = (N_NODES + 7) / 8;              // 8 warps/block
    const int SPMM_BLOCKS = ((NNZ / 2) * 16 + 255) / 256;   // 2 edges/thread

    k_init<<<ROWS_BLOCKS, 256>>>(up, ip);

    k_spmm<<<SPMM_BLOCKS, 256>>>(erow, ecol, eval, 1);
    k_norm<<<ROWS_BLOCKS, 256>>>(1);                        // norm p1, zero p2
    k_spmm<<<SPMM_BLOCKS, 256>>>(erow, ecol, eval, 2);
    k_norm<<<ROWS_BLOCKS, 256>>>(2);                        // norm p2, zero p3
    k_spmm<<<SPMM_BLOCKS, 256>>>(erow, ecol, eval, 3);      // p3 left raw

    k_score<<<(BATCH + 7) / 8, 256>>>(users, adj, weak, strong, out);
}

// round 6
// speedup vs baseline: 1.6664x; 1.0513x over previous
#include <cuda_runtime.h>
#include <cuda_fp16.h>

#define NUM_USERS 100000
#define NUM_ITEMS 50000
#define N_NODES   150000
#define C         64
#define NNZ       2400000
#define BATCH     8192
#define NEG_SLOPE 0.1f
#define EPS       1e-12f

// Normalized layer outputs p0,p1,p2 stored fp16 (gather/score source).
__device__ __half g_h[3][(size_t)N_NODES * C];
// fp32 RED accumulation targets (ping-pong). Layer1->rawA, 2->rawB, 3->rawA.
__device__ float g_rawA[(size_t)N_NODES * C];
__device__ float g_rawB[(size_t)N_NODES * C];

__device__ __forceinline__ float lrelu(float x) {
    return x >= 0.0f ? x : NEG_SLOPE * x;
}

__device__ __forceinline__ float warp_sum(float s) {
#pragma unroll
    for (int o = 16; o; o >>= 1) s += __shfl_xor_sync(0xffffffffu, s, o);
    return s;
}

// ---------------- init: normalize prefs -> h0 (fp16), zero rawA ----------------
__global__ __launch_bounds__(256) void k_init(const float* __restrict__ up,
                                              const float* __restrict__ ip) {
    int row = blockIdx.x * (blockDim.x >> 5) + (threadIdx.x >> 5);
    if (row >= N_NODES) return;
    int lane = threadIdx.x & 31;

    const float* src = (row < NUM_USERS)
                           ? (up + (size_t)row * C)
                           : (ip + (size_t)(row - NUM_USERS) * C);
    float2 v = reinterpret_cast<const float2*>(src)[lane];
    v.x = lrelu(v.x);
    v.y = lrelu(v.y);
    float s = warp_sum(v.x * v.x + v.y * v.y);
    float inv = 1.0f / fmaxf(sqrtf(s), EPS);
    v.x *= inv; v.y *= inv;

    size_t idx = (size_t)row * 32 + lane;
    reinterpret_cast<__half2*>(g_h[0])[idx] = __float22half2_rn(v);
    reinterpret_cast<float2*>(g_rawA)[idx] = make_float2(0.0f, 0.0f);
}

// ---------------- SpMM scatter: 16 threads/edge, 2 edges/thread ----------------
// Gathers fp16 rows (128 B/edge), REDs fp32 (256 B/edge).
__global__ __launch_bounds__(256) void k_spmm(const int* __restrict__ erow,
                                              const int* __restrict__ ecol,
                                              const float* __restrict__ eval,
                                              int layer) {
    const __half* __restrict__ p =
        (layer == 1) ? g_h[0] : (layer == 2) ? g_h[1] : g_h[2];
    float* __restrict__ pn = (layer == 2) ? g_rawB : g_rawA;

    int tid = blockIdx.x * blockDim.x + threadIdx.x;
    int e0 = tid >> 4;
    int q  = tid & 15;
    if (e0 >= NNZ / 2) return;
    int e1 = e0 + NNZ / 2;

    int   r0 = erow[e0], c0 = ecol[e0];
    int   r1 = erow[e1], c1 = ecol[e1];
    float v0 = eval[e0], v1 = eval[e1];

    // 4 halves per lane (8 B), 16 lanes = full 64-feature row
    uint2 ha = __ldg(reinterpret_cast<const uint2*>(p + (size_t)c0 * C + q * 4));
    uint2 hb = __ldg(reinterpret_cast<const uint2*>(p + (size_t)c1 * C + q * 4));

    float2 a01 = __half22float2(*reinterpret_cast<__half2*>(&ha.x));
    float2 a23 = __half22float2(*reinterpret_cast<__half2*>(&ha.y));
    float2 b01 = __half22float2(*reinterpret_cast<__half2*>(&hb.x));
    float2 b23 = __half22float2(*reinterpret_cast<__half2*>(&hb.y));

    float4 x0 = make_float4(a01.x * v0, a01.y * v0, a23.x * v0, a23.y * v0);
    float4 x1 = make_float4(b01.x * v1, b01.y * v1, b23.x * v1, b23.y * v1);

    float* d0 = pn + (size_t)r0 * C + q * 4;
    float* d1 = pn + (size_t)r1 * C + q * 4;
    asm volatile("red.global.add.v4.f32 [%0], {%1,%2,%3,%4};"
                 :: "l"(d0), "f"(x0.x), "f"(x0.y), "f"(x0.z), "f"(x0.w) : "memory");
    asm volatile("red.global.add.v4.f32 [%0], {%1,%2,%3,%4};"
                 :: "l"(d1), "f"(x1.x), "f"(x1.y), "f"(x1.z), "f"(x1.w) : "memory");
}

// ---------------- norm: raw fp32 -> lrelu+l2norm -> fp16, zero next raw ----------------
// layer==1: rawA -> h1, zero rawB.  layer==2: rawB -> h2, zero rawA.
__global__ __launch_bounds__(256) void k_norm(int layer) {
    const float* __restrict__ raw = (layer == 1) ? g_rawA : g_rawB;
    __half* __restrict__ hdst     = g_h[layer];
    float* __restrict__ rawz      = (layer == 1) ? g_rawB : g_rawA;

    int row = blockIdx.x * (blockDim.x >> 5) + (threadIdx.x >> 5);
    if (row >= N_NODES) return;
    int lane = threadIdx.x & 31;
    size_t idx = (size_t)row * 32 + lane;

    float2 v = reinterpret_cast<const float2*>(raw)[idx];
    v.x = lrelu(v.x);
    v.y = lrelu(v.y);
    float s = warp_sum(v.x * v.x + v.y * v.y);
    float inv = 1.0f / fmaxf(sqrtf(s), EPS);
    v.x *= inv; v.y *= inv;

    reinterpret_cast<__half2*>(hdst)[idx] = __float22half2_rn(v);
    reinterpret_cast<float2*>(rawz)[idx] = make_float2(0.0f, 0.0f);
}

// ---------------- scoring ----------------
// merged*4 = h0 + h1 + h2 + norm(rawA) at the needed rows.
__device__ __forceinline__ float2 merged_row(int row, int lane) {
    size_t idx = (size_t)row * 32 + lane;

    __half2 h0 = __ldg(&reinterpret_cast<const __half2*>(g_h[0])[idx]);
    __half2 h1 = __ldg(&reinterpret_cast<const __half2*>(g_h[1])[idx]);
    __half2 h2 = __ldg(&reinterpret_cast<const __half2*>(g_h[2])[idx]);
    float2 a3  = __ldg(&reinterpret_cast<const float2*>(g_rawA)[idx]);

    a3.x = lrelu(a3.x);
    a3.y = lrelu(a3.y);
    float s = warp_sum(a3.x * a3.x + a3.y * a3.y);
    float inv = 1.0f / fmaxf(sqrtf(s), EPS);

    float2 f0 = __half22float2(h0);
    float2 f1 = __half22float2(h1);
    float2 f2 = __half22float2(h2);

    float2 m;
    m.x = f0.x + f1.x + f2.x + a3.x * inv;
    m.y = f0.y + f1.y + f2.y + a3.y * inv;
    return m;
}

__global__ __launch_bounds__(256) void k_score(const int* __restrict__ users,
                                               const int* __restrict__ adj,
                                               const int* __restrict__ weak,
                                               const int* __restrict__ strong,
                                               float* __restrict__ out) {
    int b = blockIdx.x * (blockDim.x >> 5) + (threadIdx.x >> 5);
    if (b >= BATCH) return;
    int lane = threadIdx.x & 31;

    float2 uv = merged_row(users[b], lane);
    float2 m0 = merged_row(NUM_USERS + adj[b], lane);
    float2 m1 = merged_row(NUM_USERS + weak[b], lane);
    float2 m2 = merged_row(NUM_USERS + strong[b], lane);

    float d0 = warp_sum(uv.x * m0.x + uv.y * m0.y);
    float d1 = warp_sum(uv.x * m1.x + uv.y * m1.y);
    float d2 = warp_sum(uv.x * m2.x + uv.y * m2.y);

    if (lane == 0) {
        out[0 * BATCH + b] = 1.0f / (1.0f + expf(-d0 * (1.0f / 16.0f)));
        out[1 * BATCH + b] = 1.0f / (1.0f + expf(-d1 * (1.0f / 16.0f)));
        out[2 * BATCH + b] = 1.0f / (1.0f + expf(-d2 * (1.0f / 16.0f)));
    }
}

extern "C" void kernel_launch(void* const* d_in, const int* in_sizes, int n_in,
                              void* d_out, int out_size) {
    const int*   users  = (const int*)d_in[0];
    const int*   adj    = (const int*)d_in[1];
    const int*   weak   = (const int*)d_in[2];
    const int*   strong = (const int*)d_in[3];
    const int*   erow   = (const int*)d_in[4];
    const int*   ecol   = (const int*)d_in[5];
    const float* eval   = (const float*)d_in[6];
    const float* up     = (const float*)d_in[7];
    const float* ip     = (const float*)d_in[8];
    float* out = (float*)d_out;

    const int ROWS_BLOCKS = (N_NODES + 7) / 8;              // 8 warps/block
    const int SPMM_BLOCKS = ((NNZ / 2) * 16 + 255) / 256;   // 2 edges/thread

    k_init<<<ROWS_BLOCKS, 256>>>(up, ip);

    k_spmm<<<SPMM_BLOCKS, 256>>>(erow, ecol, eval, 1);   // h0 -> rawA
    k_norm<<<ROWS_BLOCKS, 256>>>(1);                     // rawA -> h1, zero rawB
    k_spmm<<<SPMM_BLOCKS, 256>>>(erow, ecol, eval, 2);   // h1 -> rawB
    k_norm<<<ROWS_BLOCKS, 256>>>(2);                     // rawB -> h2, zero rawA
    k_spmm<<<SPMM_BLOCKS, 256>>>(erow, ecol, eval, 3);   // h2 -> rawA (raw)

    k_score<<<(BATCH + 7) / 8, 256>>>(users, adj, weak, strong, out);
}

// round 8
// speedup vs baseline: 2.6139x; 1.5686x over previous
#include <cuda_runtime.h>
#include <cuda_fp16.h>
#include <cstdint>

#define NUM_USERS 100000
#define NUM_ITEMS 50000
#define N_NODES   150000
#define C         64
#define NNZ       2400000
#define BATCH     8192
#define NEG_SLOPE 0.1f
#define EPS       1e-12f

// Normalized layer outputs p0,p1,p2 in fp16 (gather/score sources).
__device__ __half g_h[3][(size_t)N_NODES * C];
// fp16 RED accumulation targets (ping-pong). Layer1->rawA, 2->rawB, 3->rawA.
__device__ __half g_rawA[(size_t)N_NODES * C];
__device__ __half g_rawB[(size_t)N_NODES * C];

__device__ __forceinline__ float lrelu(float x) {
    return x >= 0.0f ? x : NEG_SLOPE * x;
}

__device__ __forceinline__ float warp_sum(float s) {
#pragma unroll
    for (int o = 16; o; o >>= 1) s += __shfl_xor_sync(0xffffffffu, s, o);
    return s;
}

// ---------------- init: normalize prefs -> h0 (fp16), zero rawA ----------------
__global__ __launch_bounds__(256) void k_init(const float* __restrict__ up,
                                              const float* __restrict__ ip) {
    int row = blockIdx.x * (blockDim.x >> 5) + (threadIdx.x >> 5);
    if (row >= N_NODES) return;
    int lane = threadIdx.x & 31;

    const float* src = (row < NUM_USERS)
                           ? (up + (size_t)row * C)
                           : (ip + (size_t)(row - NUM_USERS) * C);
    float2 v = reinterpret_cast<const float2*>(src)[lane];
    v.x = lrelu(v.x);
    v.y = lrelu(v.y);
    float s = warp_sum(v.x * v.x + v.y * v.y);
    float inv = 1.0f / fmaxf(sqrtf(s), EPS);
    v.x *= inv; v.y *= inv;

    size_t idx = (size_t)row * 32 + lane;
    reinterpret_cast<__half2*>(g_h[0])[idx] = __float22half2_rn(v);
    reinterpret_cast<__half2*>(g_rawA)[idx] = __half2half2(__ushort_as_half(0));
}

// ---------------- SpMM scatter ----------------
// 8 threads/edge (8 features each), 2 edges/thread.
// Gather 16 B fp16, RED 16 B fp16 (red.global.add.noftz.v4.f16x2).
__global__ __launch_bounds__(256) void k_spmm(const int* __restrict__ erow,
                                              const int* __restrict__ ecol,
                                              const float* __restrict__ eval,
                                              int layer) {
    const __half* __restrict__ p =
        (layer == 1) ? g_h[0] : (layer == 2) ? g_h[1] : g_h[2];
    __half* __restrict__ pn = (layer == 2) ? g_rawB : g_rawA;

    int tid = blockIdx.x * blockDim.x + threadIdx.x;
    int e0 = tid >> 3;
    int q  = tid & 7;
    if (e0 >= NNZ / 2) return;
    int e1 = e0 + NNZ / 2;

    int   r0 = erow[e0], c0 = ecol[e0];
    int   r1 = erow[e1], c1 = ecol[e1];
    float v0 = eval[e0], v1 = eval[e1];

    // 8 halves per lane (16 B); 8 lanes cover the 64-feature row
    uint4 ha = __ldg(reinterpret_cast<const uint4*>(p + (size_t)c0 * C + q * 8));
    uint4 hb = __ldg(reinterpret_cast<const uint4*>(p + (size_t)c1 * C + q * 8));

    // scale in fp32, repack to half2
    unsigned int o0[4], o1[4];
    unsigned int* pa32 = reinterpret_cast<unsigned int*>(&ha);
    unsigned int* pb32 = reinterpret_cast<unsigned int*>(&hb);
#pragma unroll
    for (int k = 0; k < 4; ++k) {
        float2 fa = __half22float2(*reinterpret_cast<__half2*>(&pa32[k]));
        float2 fb = __half22float2(*reinterpret_cast<__half2*>(&pb32[k]));
        __half2 qa = __floats2half2_rn(fa.x * v0, fa.y * v0);
        __half2 qb = __floats2half2_rn(fb.x * v1, fb.y * v1);
        o0[k] = *reinterpret_cast<unsigned int*>(&qa);
        o1[k] = *reinterpret_cast<unsigned int*>(&qb);
    }

    __half* d0 = pn + (size_t)r0 * C + q * 8;
    __half* d1 = pn + (size_t)r1 * C + q * 8;
    asm volatile("red.global.add.noftz.v4.f16x2 [%0], {%1,%2,%3,%4};"
                 :: "l"(d0), "r"(o0[0]), "r"(o0[1]), "r"(o0[2]), "r"(o0[3]) : "memory");
    asm volatile("red.global.add.noftz.v4.f16x2 [%0], {%1,%2,%3,%4};"
                 :: "l"(d1), "r"(o1[0]), "r"(o1[1]), "r"(o1[2]), "r"(o1[3]) : "memory");
}

// ---------------- norm: raw fp16 -> lrelu+l2norm -> fp16, zero next raw ----------------
__global__ __launch_bounds__(256) void k_norm(int layer) {
    const __half* __restrict__ raw = (layer == 1) ? g_rawA : g_rawB;
    __half* __restrict__ hdst      = g_h[layer];
    __half* __restrict__ rawz      = (layer == 1) ? g_rawB : g_rawA;

    int row = blockIdx.x * (blockDim.x >> 5) + (threadIdx.x >> 5);
    if (row >= N_NODES) return;
    int lane = threadIdx.x & 31;
    size_t idx = (size_t)row * 32 + lane;

    float2 v = __half22float2(reinterpret_cast<const __half2*>(raw)[idx]);
    v.x = lrelu(v.x);
    v.y = lrelu(v.y);
    float s = warp_sum(v.x * v.x + v.y * v.y);
    float inv = 1.0f / fmaxf(sqrtf(s), EPS);
    v.x *= inv; v.y *= inv;

    reinterpret_cast<__half2*>(hdst)[idx] = __float22half2_rn(v);
    reinterpret_cast<__half2*>(rawz)[idx] = __half2half2(__ushort_as_half(0));
}

// ---------------- scoring ----------------
// merged*4 = h0 + h1 + h2 + norm(rawA) at the needed rows.
__device__ __forceinline__ float2 merged_row(int row, int lane) {
    size_t idx = (size_t)row * 32 + lane;

    __half2 h0 = __ldg(&reinterpret_cast<const __half2*>(g_h[0])[idx]);
    __half2 h1 = __ldg(&reinterpret_cast<const __half2*>(g_h[1])[idx]);
    __half2 h2 = __ldg(&reinterpret_cast<const __half2*>(g_h[2])[idx]);
    float2 a3  = __half22float2(__ldg(&reinterpret_cast<const __half2*>(g_rawA)[idx]));

    a3.x = lrelu(a3.x);
    a3.y = lrelu(a3.y);
    float s = warp_sum(a3.x * a3.x + a3.y * a3.y);
    float inv = 1.0f / fmaxf(sqrtf(s), EPS);

    float2 f0 = __half22float2(h0);
    float2 f1 = __half22float2(h1);
    float2 f2 = __half22float2(h2);

    float2 m;
    m.x = f0.x + f1.x + f2.x + a3.x * inv;
    m.y = f0.y + f1.y + f2.y + a3.y * inv;
    return m;
}

__global__ __launch_bounds__(256) void k_score(const int* __restrict__ users,
                                               const int* __restrict__ adj,
                                               const int* __restrict__ weak,
                                               const int* __restrict__ strong,
                                               float* __restrict__ out) {
    int b = blockIdx.x * (blockDim.x >> 5) + (threadIdx.x >> 5);
    if (b >= BATCH) return;
    int lane = threadIdx.x & 31;

    float2 uv = merged_row(users[b], lane);
    float2 m0 = merged_row(NUM_USERS + adj[b], lane);
    float2 m1 = merged_row(NUM_USERS + weak[b], lane);
    float2 m2 = merged_row(NUM_USERS + strong[b], lane);

    float d0 = warp_sum(uv.x * m0.x + uv.y * m0.y);
    float d1 = warp_sum(uv.x * m1.x + uv.y * m1.y);
    float d2 = warp_sum(uv.x * m2.x + uv.y * m2.y);

    if (lane == 0) {
        out[0 * BATCH + b] = 1.0f / (1.0f + expf(-d0 * (1.0f / 16.0f)));
        out[1 * BATCH + b] = 1.0f / (1.0f + expf(-d1 * (1.0f / 16.0f)));
        out[2 * BATCH + b] = 1.0f / (1.0f + expf(-d2 * (1.0f / 16.0f)));
    }
}

extern "C" void kernel_launch(void* const* d_in, const int* in_sizes, int n_in,
                              void* d_out, int out_size) {
    const int*   users  = (const int*)d_in[0];
    const int*   adj    = (const int*)d_in[1];
    const int*   weak   = (const int*)d_in[2];
    const int*   strong = (const int*)d_in[3];
    const int*   erow   = (const int*)d_in[4];
    const int*   ecol   = (const int*)d_in[5];
    const float* eval   = (const float*)d_in[6];
    const float* up     = (const float*)d_in[7];
    const float* ip     = (const float*)d_in[8];
    float* out = (float*)d_out;

    const int ROWS_BLOCKS = (N_NODES + 7) / 8;             // 8 warps/block
    const int SPMM_BLOCKS = ((NNZ / 2) * 8 + 255) / 256;   // 8 lanes/edge, 2 edges/thread

    k_init<<<ROWS_BLOCKS, 256>>>(up, ip);

    k_spmm<<<SPMM_BLOCKS, 256>>>(erow, ecol, eval, 1);   // h0 -> rawA
    k_norm<<<ROWS_BLOCKS, 256>>>(1);                     // rawA -> h1, zero rawB
    k_spmm<<<SPMM_BLOCKS, 256>>>(erow, ecol, eval, 2);   // h1 -> rawB
    k_norm<<<ROWS_BLOCKS, 256>>>(2);                     // rawB -> h2, zero rawA
    k_spmm<<<SPMM_BLOCKS, 256>>>(erow, ecol, eval, 3);   // h2 -> rawA (raw)

    k_score<<<(BATCH + 7) / 8, 256>>>(users, adj, weak, strong, out);
}

// round 9
// speedup vs baseline: 2.7303x; 1.0445x over previous
#include <cuda_runtime.h>
#include <cuda_fp16.h>
#include <cstdint>

#define NUM_USERS 100000
#define NUM_ITEMS 50000
#define N_NODES   150000
#define C         64
#define NNZ       2400000
#define BATCH     8192
#define NEG_SLOPE 0.1f
#define EPS       1e-12f

// Normalized layer outputs p0,p1,p2 in fp16 (gather/score sources).
__device__ __half g_h[3][(size_t)N_NODES * C];
// fp16 RED accumulation targets (ping-pong). Layer1->rawA, 2->rawB, 3->rawA.
__device__ __half g_rawA[(size_t)N_NODES * C];
__device__ __half g_rawB[(size_t)N_NODES * C];
// Which rows layer-3 output is actually read at (batch rows only).
__device__ unsigned char g_needed[N_NODES];

__device__ __forceinline__ float lrelu(float x) {
    return x >= 0.0f ? x : NEG_SLOPE * x;
}

__device__ __forceinline__ float warp_sum(float s) {
#pragma unroll
    for (int o = 16; o; o >>= 1) s += __shfl_xor_sync(0xffffffffu, s, o);
    return s;
}

// ---------------- needed-row bitmap ----------------
__global__ __launch_bounds__(256) void k_zero_needed() {
    int i = blockIdx.x * blockDim.x + threadIdx.x;
    if (i * 4 < N_NODES) {
        // N_NODES not divisible by 4? 150000/4=37500 exact.
        reinterpret_cast<unsigned int*>(g_needed)[i] = 0u;
    }
}

__global__ __launch_bounds__(256) void k_mark(const int* __restrict__ users,
                                              const int* __restrict__ adj,
                                              const int* __restrict__ weak,
                                              const int* __restrict__ strong) {
    int i = blockIdx.x * blockDim.x + threadIdx.x;
    if (i >= BATCH) return;
    g_needed[users[i]] = 1;
    g_needed[NUM_USERS + adj[i]] = 1;
    g_needed[NUM_USERS + weak[i]] = 1;
    g_needed[NUM_USERS + strong[i]] = 1;
}

// ---------------- init: normalize prefs -> h0 (fp16), zero rawA ----------------
__global__ __launch_bounds__(256) void k_init(const float* __restrict__ up,
                                              const float* __restrict__ ip) {
    int row = blockIdx.x * (blockDim.x >> 5) + (threadIdx.x >> 5);
    if (row >= N_NODES) return;
    int lane = threadIdx.x & 31;

    const float* src = (row < NUM_USERS)
                           ? (up + (size_t)row * C)
                           : (ip + (size_t)(row - NUM_USERS) * C);
    float2 v = reinterpret_cast<const float2*>(src)[lane];
    v.x = lrelu(v.x);
    v.y = lrelu(v.y);
    float s = warp_sum(v.x * v.x + v.y * v.y);
    float inv = 1.0f / fmaxf(sqrtf(s), EPS);
    v.x *= inv; v.y *= inv;

    size_t idx = (size_t)row * 32 + lane;
    reinterpret_cast<__half2*>(g_h[0])[idx] = __float22half2_rn(v);
    reinterpret_cast<__half2*>(g_rawA)[idx] = __half2half2(__ushort_as_half(0));
}

// ---------------- SpMM scatter ----------------
// 8 threads/edge (8 features each), 4 edges/thread.
// Gather 16 B fp16, RED 16 B fp16 (red.global.add.noftz.v4.f16x2).
// FILTER: when nonzero, edges whose destination row is not in g_needed are
// skipped entirely (no gather, no RED) — valid only for the final layer.
template <bool FILTER>
__global__ __launch_bounds__(256) void k_spmm(const int* __restrict__ erow,
                                              const int* __restrict__ ecol,
                                              const float* __restrict__ eval,
                                              int layer) {
    const __half* __restrict__ p =
        (layer == 1) ? g_h[0] : (layer == 2) ? g_h[1] : g_h[2];
    __half* __restrict__ pn = (layer == 2) ? g_rawB : g_rawA;

    int tid = blockIdx.x * blockDim.x + threadIdx.x;
    int e = tid >> 3;
    int q = tid & 7;
    if (e >= NNZ / 4) return;

    int eidx[4];
    eidx[0] = e;
    eidx[1] = e + NNZ / 4;
    eidx[2] = e + NNZ / 2;
    eidx[3] = e + 3 * (NNZ / 4);

    int r[4];
    bool act[4];
#pragma unroll
    for (int k = 0; k < 4; ++k) {
        r[k] = erow[eidx[k]];
        act[k] = FILTER ? (g_needed[r[k]] != 0) : true;
    }

    int   c[4];
    float v[4];
    uint4 h[4];
#pragma unroll
    for (int k = 0; k < 4; ++k) {
        if (act[k]) {
            c[k] = ecol[eidx[k]];
            v[k] = eval[eidx[k]];
            h[k] = __ldg(reinterpret_cast<const uint4*>(p + (size_t)c[k] * C + q * 8));
        }
    }

#pragma unroll
    for (int k = 0; k < 4; ++k) {
        if (act[k]) {
            unsigned int o[4];
            unsigned int* hh = reinterpret_cast<unsigned int*>(&h[k]);
#pragma unroll
            for (int j = 0; j < 4; ++j) {
                float2 f = __half22float2(*reinterpret_cast<__half2*>(&hh[j]));
                __half2 qv = __floats2half2_rn(f.x * v[k], f.y * v[k]);
                o[j] = *reinterpret_cast<unsigned int*>(&qv);
            }
            __half* d = pn + (size_t)r[k] * C + q * 8;
            asm volatile("red.global.add.noftz.v4.f16x2 [%0], {%1,%2,%3,%4};"
                         :: "l"(d), "r"(o[0]), "r"(o[1]), "r"(o[2]), "r"(o[3])
                         : "memory");
        }
    }
}

// ---------------- norm: raw fp16 -> lrelu+l2norm -> fp16, zero next raw ----------------
__global__ __launch_bounds__(256) void k_norm(int layer) {
    const __half* __restrict__ raw = (layer == 1) ? g_rawA : g_rawB;
    __half* __restrict__ hdst      = g_h[layer];
    __half* __restrict__ rawz      = (layer == 1) ? g_rawB : g_rawA;

    int row = blockIdx.x * (blockDim.x >> 5) + (threadIdx.x >> 5);
    if (row >= N_NODES) return;
    int lane = threadIdx.x & 31;
    size_t idx = (size_t)row * 32 + lane;

    float2 v = __half22float2(reinterpret_cast<const __half2*>(raw)[idx]);
    v.x = lrelu(v.x);
    v.y = lrelu(v.y);
    float s = warp_sum(v.x * v.x + v.y * v.y);
    float inv = 1.0f / fmaxf(sqrtf(s), EPS);
    v.x *= inv; v.y *= inv;

    reinterpret_cast<__half2*>(hdst)[idx] = __float22half2_rn(v);
    reinterpret_cast<__half2*>(rawz)[idx] = __half2half2(__ushort_as_half(0));
}

// ---------------- scoring ----------------
// merged*4 = h0 + h1 + h2 + norm(rawA) at the needed rows.
__device__ __forceinline__ float2 merged_row(int row, int lane) {
    size_t idx = (size_t)row * 32 + lane;

    __half2 h0 = __ldg(&reinterpret_cast<const __half2*>(g_h[0])[idx]);
    __half2 h1 = __ldg(&reinterpret_cast<const __half2*>(g_h[1])[idx]);
    __half2 h2 = __ldg(&reinterpret_cast<const __half2*>(g_h[2])[idx]);
    float2 a3  = __half22float2(__ldg(&reinterpret_cast<const __half2*>(g_rawA)[idx]));

    a3.x = lrelu(a3.x);
    a3.y = lrelu(a3.y);
    float s = warp_sum(a3.x * a3.x + a3.y * a3.y);
    float inv = 1.0f / fmaxf(sqrtf(s), EPS);

    float2 f0 = __half22float2(h0);
    float2 f1 = __half22float2(h1);
    float2 f2 = __half22float2(h2);

    float2 m;
    m.x = f0.x + f1.x + f2.x + a3.x * inv;
    m.y = f0.y + f1.y + f2.y + a3.y * inv;
    return m;
}

__global__ __launch_bounds__(256) void k_score(const int* __restrict__ users,
                                               const int* __restrict__ adj,
                                               const int* __restrict__ weak,
                                               const int* __restrict__ strong,
                                               float* __restrict__ out) {
    int b = blockIdx.x * (blockDim.x >> 5) + (threadIdx.x >> 5);
    if (b >= BATCH) return;
    int lane = threadIdx.x & 31;

    float2 uv = merged_row(users[b], lane);
    float2 m0 = merged_row(NUM_USERS + adj[b], lane);
    float2 m1 = merged_row(NUM_USERS + weak[b], lane);
    float2 m2 = merged_row(NUM_USERS + strong[b], lane);

    float d0 = warp_sum(uv.x * m0.x + uv.y * m0.y);
    float d1 = warp_sum(uv.x * m1.x + uv.y * m1.y);
    float d2 = warp_sum(uv.x * m2.x + uv.y * m2.y);

    if (lane == 0) {
        out[0 * BATCH + b] = 1.0f / (1.0f + expf(-d0 * (1.0f / 16.0f)));
        out[1 * BATCH + b] = 1.0f / (1.0f + expf(-d1 * (1.0f / 16.0f)));
        out[2 * BATCH + b] = 1.0f / (1.0f + expf(-d2 * (1.0f / 16.0f)));
    }
}

extern "C" void kernel_launch(void* const* d_in, const int* in_sizes, int n_in,
                              void* d_out, int out_size) {
    const int*   users  = (const int*)d_in[0];
    const int*   adj    = (const int*)d_in[1];
    const int*   weak   = (const int*)d_in[2];
    const int*   strong = (const int*)d_in[3];
    const int*   erow   = (const int*)d_in[4];
    const int*   ecol   = (const int*)d_in[5];
    const float* eval   = (const float*)d_in[6];
    const float* up     = (const float*)d_in[7];
    const float* ip     = (const float*)d_in[8];
    float* out = (float*)d_out;

    const int ROWS_BLOCKS = (N_NODES + 7) / 8;             // 8 warps/block
    const int SPMM_BLOCKS = ((NNZ / 4) * 8 + 255) / 256;   // 8 lanes/edge, 4 edges/thread

    // needed-row bitmap for the final layer
    k_zero_needed<<<(N_NODES / 4 + 255) / 256, 256>>>();
    k_mark<<<(BATCH + 255) / 256, 256>>>(users, adj, weak, strong);

    k_init<<<ROWS_BLOCKS, 256>>>(up, ip);

    k_spmm<false><<<SPMM_BLOCKS, 256>>>(erow, ecol, eval, 1);  // h0 -> rawA
    k_norm<<<ROWS_BLOCKS, 256>>>(1);                           // rawA -> h1, zero rawB
    k_spmm<false><<<SPMM_BLOCKS, 256>>>(erow, ecol, eval, 2);  // h1 -> rawB
    k_norm<<<ROWS_BLOCKS, 256>>>(2);                           // rawB -> h2, zero rawA
    k_spmm<true><<<SPMM_BLOCKS, 256>>>(erow, ecol, eval, 3);   // h2 -> rawA (filtered)

    k_score<<<(BATCH + 7) / 8, 256>>>(users, adj, weak, strong, out);
}